// round 14
// baseline (speedup 1.0000x reference)
#include <cuda_runtime.h>
#include <cuda_fp16.h>
#include <math.h>
#include <stdint.h>

#define NN 50000
#define DD 128
#define HH 8
#define DHH 16
#define EE 800000
#define DFF 512
#define NBLK_SCAN 196   // ceil(50000/256)
#define NTILES 391      // ceil(50000/128)

// ---------------- scratch (static device globals; no allocation) ----------------
__device__ __half    g_zh[NN * DD];              // z, half, row-major
__device__ uint32_t  g_lnf[NTILES * 4 * 2048];   // LN out, A-fragment layout (K=128)
__device__ uint32_t  g_intf[NTILES * 16 * 2048]; // FFN inter, A-fragment layout (K=512)
__device__ uint32_t  g_wtp[4 * 2048];            // W_fc^T, B-fragment layout [c][2048]
__device__ uint32_t  g_w1p[4 * 4 * 2048];        // W1, B-fragment [c][nt][2048]
__device__ uint32_t  g_w2p[16 * 2048];           // W2, B-fragment [c][2048]
__device__ float g_el[NN * HH];
__device__ float g_er[NN * HH];
__device__ uint32_t g_wsh[EE * 4];               // edge weights, half2 x4
__device__ int   g_srcs[EE];
__device__ int   g_rank[EE];                     // edge rank within its dst segment
__device__ int   g_deg[NN];
__device__ int   g_base[NN];
__device__ int   g_bsum[256];
__device__ int   g_boff[256];
__device__ float g_hres[NN * DD];

__device__ __forceinline__ uint32_t f2h2(float lo, float hi) {
    __half2 h = __floats2half2_rn(lo, hi);
    return *(uint32_t*)&h;
}

// decode B-frag word index (within 2048-word block) -> (k0, n_local)
__device__ __forceinline__ void bfrag_decode(int rest, int& g, int& pl, int& nloc) {
    int blk = rest >> 6, off = rest & 63;
    g = blk >> 4;
    int u = blk & 15;
    int lw = off >> 1, iw = off & 1;
    pl = (lw & 3) + 4 * iw;
    nloc = u * 8 + (lw >> 2);
}

// ---------------- fused prep: zero counters + build fragment-layout weights ------
__global__ void prep_kernel(const float* __restrict__ wfc,
                            const float* __restrict__ W1,
                            const float* __restrict__ W2) {
    int i = blockIdx.x * blockDim.x + threadIdx.x;
    if (i < NN) g_deg[i] = 0;
    if (i < 4 * 2048) {
        int c = i >> 11, rest = i & 2047;
        int g, pl, n;
        bfrag_decode(rest, g, pl, n);
        int k0 = c * 32 + (g * 8 + pl) * 2;
        float v0 = wfc[(n >> 4) * 2048 + k0 * 16 + (n & 15)];
        float v1 = wfc[(n >> 4) * 2048 + (k0 + 1) * 16 + (n & 15)];
        g_wtp[i] = f2h2(v0, v1);
    }
    if (i < 4 * 4 * 2048) {
        int c = i >> 13, nt = (i >> 11) & 3, rest = i & 2047;
        int g, pl, nl;
        bfrag_decode(rest, g, pl, nl);
        int n = nt * 128 + nl;
        int k0 = c * 32 + (g * 8 + pl) * 2;
        g_w1p[i] = f2h2(W1[(size_t)k0 * DFF + n], W1[(size_t)(k0 + 1) * DFF + n]);
    }
    if (i < 16 * 2048) {
        int c = i >> 11, rest = i & 2047;
        int g, pl, n;
        bfrag_decode(rest, g, pl, n);
        int k0 = c * 32 + (g * 8 + pl) * 2;
        g_w2p[i] = f2h2(W2[(size_t)k0 * DD + n], W2[(size_t)(k0 + 1) * DD + n]);
    }
}

// ---------------- fp16 mma ----------------
__device__ __forceinline__ void mma_f16(float* c, const uint32_t* a, const uint32_t* b) {
    asm volatile(
        "mma.sync.aligned.m16n8k16.row.col.f32.f16.f16.f32 "
        "{%0,%1,%2,%3}, {%4,%5,%6,%7}, {%8,%9}, {%0,%1,%2,%3};"
        : "+f"(c[0]), "+f"(c[1]), "+f"(c[2]), "+f"(c[3])
        : "r"(a[0]), "r"(a[1]), "r"(a[2]), "r"(a[3]), "r"(b[0]), "r"(b[1]));
}

#define A_G_STRIDE 1028
#define B_U_STRIDE 68

// ---------------- fp16 tensor GEMM, 128x128 tile, 256 threads, smem dbuf ---------
template <int EPI, int AFRAG, int CMODE>
__global__ void __launch_bounds__(256, 2) tgemm_kernel(
    const void* __restrict__ Av, const uint32_t* __restrict__ Bp, void* __restrict__ Cv,
    int M, int Nn, int K, const float* __restrict__ bias, const float* __restrict__ res)
{
    __shared__ uint32_t Af[2][2 * A_G_STRIDE];
    __shared__ uint32_t Bf[2][2 * 16 * B_U_STRIDE];

    const float* A32 = (const float*)Av;
    const uint32_t* Afr = (const uint32_t*)Av;
    float* Cf = (float*)Cv;
    __half* Ch = (__half*)Cv;
    uint32_t* Cfr = (uint32_t*)Cv;

    const int tid = threadIdx.x;
    const int lane = tid & 31;
    const int wid = tid >> 5;
    const int wm = wid >> 2;
    const int wn = wid & 3;
    const int m0 = blockIdx.x * 128;
    const int n0 = blockIdx.y * 128;
    const int KC = K >> 5;
    const int NT = Nn >> 7;

    const int a_m = tid >> 3;
    const int a_kq = tid & 7;
    const int bblk = tid >> 4;
    const int boff = (4 * tid) & 63;

    uint32_t aw[8];
    uint4 av0, av1, bv0, bv1;

    auto ldg_chunk = [&](int c) {
        if constexpr (AFRAG) {
            const uint4* s = (const uint4*)(Afr + ((size_t)blockIdx.x * KC + c) * 2048);
            av0 = s[tid];
            av1 = s[tid + 256];
        } else {
            const int k0 = c * 32;
#pragma unroll
            for (int it = 0; it < 4; ++it) {
                int ml = a_m + it * 32;
                float4 v = make_float4(0.f, 0.f, 0.f, 0.f);
                if (m0 + ml < M) v = *(const float4*)&A32[(size_t)(m0 + ml) * K + k0 + a_kq * 4];
                aw[it * 2 + 0] = f2h2(v.x, v.y);
                aw[it * 2 + 1] = f2h2(v.z, v.w);
            }
        }
        const uint4* s = (const uint4*)(Bp + ((size_t)(c * NT + blockIdx.y)) * 2048);
        bv0 = s[tid];
        bv1 = s[tid + 256];
    };

    auto sts_chunk = [&](int buf) {
        if constexpr (AFRAG) {
            *(uint4*)&Af[buf][4 * tid] = av0;
            *(uint4*)&Af[buf][A_G_STRIDE + 4 * tid] = av1;
        } else {
#pragma unroll
            for (int it = 0; it < 4; ++it) {
                int ml = a_m + it * 32;
                int t4 = ml >> 4;
                int mr = ml & 15;
#pragma unroll
                for (int j = 0; j < 2; ++j) {
                    int p = 2 * a_kq + j;
                    int g = p >> 3, pl = p & 7;
                    int lw = (mr & 7) * 4 + (pl & 3);
                    int iw = (mr >> 3) + 2 * (pl >> 2);
                    Af[buf][g * A_G_STRIDE + t4 * 128 + lw * 4 + iw] = aw[it * 2 + j];
                }
            }
        }
        *(uint4*)&Bf[buf][bblk * B_U_STRIDE + boff] = bv0;
        *(uint4*)&Bf[buf][(16 + bblk) * B_U_STRIDE + boff] = bv1;
    };

    float acc[4][4][4];
#pragma unroll
    for (int i = 0; i < 4; ++i)
#pragma unroll
        for (int j = 0; j < 4; ++j)
#pragma unroll
            for (int r = 0; r < 4; ++r) acc[i][j][r] = 0.f;

    auto mma_chunk = [&](int buf) {
#pragma unroll
        for (int g = 0; g < 2; ++g) {
            uint32_t af[4][4], bf[4][2];
#pragma unroll
            for (int mt = 0; mt < 4; ++mt)
                *(uint4*)af[mt] = *(const uint4*)&Af[buf][g * A_G_STRIDE + (wm * 4 + mt) * 128 + lane * 4];
#pragma unroll
            for (int nt = 0; nt < 4; ++nt)
                *(uint2*)bf[nt] = *(const uint2*)&Bf[buf][(g * 16 + wn * 4 + nt) * B_U_STRIDE + lane * 2];
#pragma unroll
            for (int mt = 0; mt < 4; ++mt)
#pragma unroll
                for (int nt = 0; nt < 4; ++nt)
                    mma_f16(acc[mt][nt], af[mt], bf[nt]);
        }
    };

    ldg_chunk(0);
    sts_chunk(0);
    __syncthreads();
    for (int c = 1; c < KC; ++c) {
        ldg_chunk(c);
        mma_chunk((c - 1) & 1);
        sts_chunk(c & 1);
        __syncthreads();
    }
    mma_chunk((KC - 1) & 1);

    // epilogue
    const int lr = lane >> 2;
    const int lc = lane & 3;
#pragma unroll
    for (int mt = 0; mt < 4; ++mt) {
#pragma unroll
        for (int nt = 0; nt < 4; ++nt) {
            int row = m0 + wm * 64 + mt * 16 + lr;
            int col = n0 + wn * 32 + nt * 8 + 2 * lc;
            float c0 = acc[mt][nt][0], c1 = acc[mt][nt][1];
            float c2 = acc[mt][nt][2], c3 = acc[mt][nt][3];
            if (EPI == 1) {
                float b0 = bias[col], b1 = bias[col + 1];
                c0 = fmaxf(c0 + b0, 0.f); c1 = fmaxf(c1 + b1, 0.f);
                c2 = fmaxf(c2 + b0, 0.f); c3 = fmaxf(c3 + b1, 0.f);
            }
            if (EPI == 2) {
                float b0 = bias[col], b1 = bias[col + 1];
                if (row < M) {
                    c0 += b0 + res[(size_t)row * Nn + col];
                    c1 += b1 + res[(size_t)row * Nn + col + 1];
                }
                if (row + 8 < M) {
                    c2 += b0 + res[(size_t)(row + 8) * Nn + col];
                    c3 += b1 + res[(size_t)(row + 8) * Nn + col + 1];
                }
            }
            if (CMODE == 0) {
                if (row < M)     *(float2*)&Cf[(size_t)row * Nn + col]       = make_float2(c0, c1);
                if (row + 8 < M) *(float2*)&Cf[(size_t)(row + 8) * Nn + col] = make_float2(c2, c3);
            } else if (CMODE == 1) {
                if (row < M)     *(uint32_t*)&Ch[(size_t)row * Nn + col]       = f2h2(c0, c1);
                if (row + 8 < M) *(uint32_t*)&Ch[(size_t)(row + 8) * Nn + col] = f2h2(c2, c3);
            } else {
                int cc = col >> 5;
                int pw = (col >> 1) & 15;
                int gg = pw >> 3, pl = pw & 7;
                size_t base = ((size_t)blockIdx.x * (Nn >> 5) + cc) * 2048 + gg * 1024;
                int m = row & 127;
                int t4 = m >> 4, mr = m & 15;
                if (row < M)
                    Cfr[base + t4 * 128 + ((mr & 7) * 4 + (pl & 3)) * 4 + ((mr >> 3) + 2 * (pl >> 2))] = f2h2(c0, c1);
                int m2 = m + 8;
                int t42 = m2 >> 4, mr2 = m2 & 15;
                if (row + 8 < M)
                    Cfr[base + t42 * 128 + ((mr2 & 7) * 4 + (pl & 3)) * 4 + ((mr2 >> 3) + 2 * (pl >> 2))] = f2h2(c2, c3);
            }
        }
    }
}

// ---------------- el / er: one thread per (node, head), z half ----------------
__global__ void eler_kernel(const float* __restrict__ a_l, const float* __restrict__ a_r) {
    int idx = blockIdx.x * blockDim.x + threadIdx.x;
    if (idx >= NN * HH) return;
    int n = idx >> 3;
    int h = idx & 7;
    const uint32_t* zw = (const uint32_t*)&g_zh[n * DD + h * DHH];
    uint4 z0 = *(const uint4*)zw;
    uint4 z1 = *(const uint4*)(zw + 4);
    uint32_t w[8] = {z0.x, z0.y, z0.z, z0.w, z1.x, z1.y, z1.z, z1.w};
    const float* lp = &a_l[h * DHH];
    const float* rp = &a_r[h * DHH];
    float pl = 0.f, pr = 0.f;
#pragma unroll
    for (int q = 0; q < 8; ++q) {
        float2 f = __half22float2(*(__half2*)&w[q]);
        pl += f.x * lp[2 * q] + f.y * lp[2 * q + 1];
        pr += f.x * rp[2 * q] + f.y * rp[2 * q + 1];
    }
    g_el[idx] = pl;
    g_er[idx] = pr;
}

// ---------------- degree histogram + per-edge rank ----------------
__global__ void deg_kernel(const int* __restrict__ edst) {
    int e = blockIdx.x * blockDim.x + threadIdx.x;
    if (e >= EE) return;
    g_rank[e] = atomicAdd(&g_deg[edst[e]], 1);
}

// ---------------- scan (2 kernels; block-offset add folded into consumers) -------
__global__ void scan1_kernel() {
    __shared__ int sh[256];
    int t = threadIdx.x;
    int i = blockIdx.x * 256 + t;
    int v = (i < NN) ? g_deg[i] : 0;
    sh[t] = v;
    __syncthreads();
#pragma unroll
    for (int off = 1; off < 256; off <<= 1) {
        int x = (t >= off) ? sh[t - off] : 0;
        __syncthreads();
        sh[t] += x;
        __syncthreads();
    }
    if (i < NN) g_base[i] = sh[t] - v;
    if (t == 255) g_bsum[blockIdx.x] = sh[255];
}
__global__ void scan2_kernel() {
    __shared__ int sh[256];
    int t = threadIdx.x;
    int v = (t < NBLK_SCAN) ? g_bsum[t] : 0;
    sh[t] = v;
    __syncthreads();
#pragma unroll
    for (int off = 1; off < 256; off <<= 1) {
        int x = (t >= off) ? sh[t - off] : 0;
        __syncthreads();
        sh[t] += x;
        __syncthreads();
    }
    g_boff[t] = sh[t] - v;
}

// ---------------- scatter (atomic-free: pos from precomputed rank) ----------------
__global__ void scatter_kernel(const int* __restrict__ esrc, const int* __restrict__ edst) {
    int e = blockIdx.x * blockDim.x + threadIdx.x;
    if (e >= EE) return;
    int s = esrc[e], d = edst[e];
    int pos = g_base[d] + g_boff[d >> 8] + g_rank[e];
    g_srcs[pos] = s;
    float4 el0 = *(const float4*)&g_el[s * HH];
    float4 el1 = *(const float4*)&g_el[s * HH + 4];
    float4 er0 = *(const float4*)&g_er[d * HH];
    float4 er1 = *(const float4*)&g_er[d * HH + 4];
    float ev[8] = {el0.x + er0.x, el0.y + er0.y, el0.z + er0.z, el0.w + er0.w,
                   el1.x + er1.x, el1.y + er1.y, el1.z + er1.z, el1.w + er1.w};
    float w[8];
#pragma unroll
    for (int h = 0; h < 8; ++h) {
        float v = ev[h];
        v = (v > 0.f) ? v : 0.01f * v;
        w[h] = __expf(v);
    }
    uint4 wv;
    wv.x = f2h2(w[0], w[1]);
    wv.y = f2h2(w[2], w[3]);
    wv.z = f2h2(w[4], w[5]);
    wv.w = f2h2(w[6], w[7]);
    *(uint4*)&g_wsh[(size_t)pos * 4] = wv;
}

// ---------------- single-pass aggregation + elu + residual + LayerNorm ----------
__global__ void __launch_bounds__(256) agg_ln_kernel(
    const float* __restrict__ x,
    const float* __restrict__ gamma, const float* __restrict__ beta)
{
    int n = blockIdx.x * 8 + (threadIdx.x >> 5);
    int lane = threadIdx.x & 31;
    if (n >= NN) return;
    int start = g_base[n] + g_boff[n >> 8];
    int deg = g_deg[n];
    int h = lane >> 2;
    float4 acc = make_float4(0.f, 0.f, 0.f, 0.f);
    float s0 = 0.f, s1 = 0.f, s2 = 0.f, s3 = 0.f;
    float s4 = 0.f, s5 = 0.f, s6 = 0.f, s7 = 0.f;
    for (int b = 0; b < deg; b += 32) {
        int cnt = min(32, deg - b);
        int mysrc = 0;
        if (lane < cnt) {
            uint4 wv = *(const uint4*)&g_wsh[(size_t)(start + b + lane) * 4];
            float2 a0 = __half22float2(*(__half2*)&wv.x);
            float2 a1 = __half22float2(*(__half2*)&wv.y);
            float2 a2 = __half22float2(*(__half2*)&wv.z);
            float2 a3 = __half22float2(*(__half2*)&wv.w);
            s0 += a0.x; s1 += a0.y; s2 += a1.x; s3 += a1.y;
            s4 += a2.x; s5 += a2.y; s6 += a3.x; s7 += a3.y;
            mysrc = g_srcs[start + b + lane];
        }
#pragma unroll 4
        for (int j = 0; j < cnt; ++j) {
            int src = __shfl_sync(0xffffffffu, mysrc, j);
            uint32_t ww = g_wsh[(size_t)(start + b + j) * 4 + (h >> 1)];
            __half2 hw = *(__half2*)&ww;
            float wv = (h & 1) ? __high2float(hw) : __low2float(hw);
            uint2 zv = *(const uint2*)&g_zh[(size_t)src * DD + lane * 4];
            float2 p0 = __half22float2(*(__half2*)&zv.x);
            float2 p1 = __half22float2(*(__half2*)&zv.y);
            acc.x = fmaf(wv, p0.x, acc.x);
            acc.y = fmaf(wv, p0.y, acc.y);
            acc.z = fmaf(wv, p1.x, acc.z);
            acc.w = fmaf(wv, p1.y, acc.w);
        }
    }
    if (deg > 0) {
#pragma unroll
        for (int o = 16; o >= 1; o >>= 1) {
            s0 += __shfl_xor_sync(0xffffffffu, s0, o);
            s1 += __shfl_xor_sync(0xffffffffu, s1, o);
            s2 += __shfl_xor_sync(0xffffffffu, s2, o);
            s3 += __shfl_xor_sync(0xffffffffu, s3, o);
            s4 += __shfl_xor_sync(0xffffffffu, s4, o);
            s5 += __shfl_xor_sync(0xffffffffu, s5, o);
            s6 += __shfl_xor_sync(0xffffffffu, s6, o);
            s7 += __shfl_xor_sync(0xffffffffu, s7, o);
        }
        float sv;
        switch (h) {
            case 0: sv = s0; break;
            case 1: sv = s1; break;
            case 2: sv = s2; break;
            case 3: sv = s3; break;
            case 4: sv = s4; break;
            case 5: sv = s5; break;
            case 6: sv = s6; break;
            default: sv = s7; break;
        }
        float inv = 1.f / fmaxf(sv, 1e-9f);
        acc.x *= inv; acc.y *= inv; acc.z *= inv; acc.w *= inv;
    }
    // ---- fused elu + residual + LayerNorm, output in A-fragment layout ----
    float4 xv = ((const float4*)(x + (size_t)n * DD))[lane];
    float4 r;
    r.x = xv.x + (acc.x > 0.f ? acc.x : expm1f(acc.x));
    r.y = xv.y + (acc.y > 0.f ? acc.y : expm1f(acc.y));
    r.z = xv.z + (acc.z > 0.f ? acc.z : expm1f(acc.z));
    r.w = xv.w + (acc.w > 0.f ? acc.w : expm1f(acc.w));
    ((float4*)(g_hres + (size_t)n * DD))[lane] = r;
    float sum = r.x + r.y + r.z + r.w;
    float sq = r.x * r.x + r.y * r.y + r.z * r.z + r.w * r.w;
#pragma unroll
    for (int o = 16; o >= 1; o >>= 1) {
        sum += __shfl_xor_sync(0xffffffffu, sum, o);
        sq  += __shfl_xor_sync(0xffffffffu, sq, o);
    }
    float mu = sum * (1.f / 128.f);
    float var = sq * (1.f / 128.f) - mu * mu;
    float rstd = rsqrtf(var + 1e-5f);
    float4 gv = ((const float4*)gamma)[lane];
    float4 bv = ((const float4*)beta)[lane];
    float o0 = (r.x - mu) * rstd * gv.x + bv.x;
    float o1 = (r.y - mu) * rstd * gv.y + bv.y;
    float o2 = (r.z - mu) * rstd * gv.z + bv.z;
    float o3 = (r.w - mu) * rstd * gv.w + bv.w;
    int T = n >> 7, m = n & 127, t4 = m >> 4, mr = m & 15;
    uint32_t wA = f2h2(o0, o1), wB = f2h2(o2, o3);
    {
        int p = 2 * lane;
        int c = p >> 4, pw = p & 15, g = pw >> 3, pl = pw & 7;
        g_lnf[((size_t)T * 4 + c) * 2048 + g * 1024 + t4 * 128 +
              ((mr & 7) * 4 + (pl & 3)) * 4 + ((mr >> 3) + 2 * (pl >> 2))] = wA;
    }
    {
        int p = 2 * lane + 1;
        int c = p >> 4, pw = p & 15, g = pw >> 3, pl = pw & 7;
        g_lnf[((size_t)T * 4 + c) * 2048 + g * 1024 + t4 * 128 +
              ((mr & 7) * 4 + (pl & 3)) * 4 + ((mr >> 3) + 2 * (pl >> 2))] = wB;
    }
}

// ---------------- launch ----------------
extern "C" void kernel_launch(void* const* d_in, const int* in_sizes, int n_in,
                              void* d_out, int out_size) {
    const float* x      = (const float*)d_in[0];
    const float* wfc    = (const float*)d_in[1];
    const float* a_l    = (const float*)d_in[2];
    const float* a_r    = (const float*)d_in[3];
    const float* gamma  = (const float*)d_in[4];
    const float* beta   = (const float*)d_in[5];
    const float* W1     = (const float*)d_in[6];
    const float* b1     = (const float*)d_in[7];
    const float* W2     = (const float*)d_in[8];
    const float* b2     = (const float*)d_in[9];
    const int* esrc     = (const int*)d_in[10];
    const int* edst     = (const int*)d_in[11];
    float* out          = (float*)d_out;

    void *p_zh, *p_lnf, *p_intf, *p_wtp, *p_w1p, *p_w2p;
    float* p_hres;
    cudaGetSymbolAddress(&p_zh, g_zh);
    cudaGetSymbolAddress(&p_lnf, g_lnf);
    cudaGetSymbolAddress(&p_intf, g_intf);
    cudaGetSymbolAddress(&p_wtp, g_wtp);
    cudaGetSymbolAddress(&p_w1p, g_w1p);
    cudaGetSymbolAddress(&p_w2p, g_w2p);
    cudaGetSymbolAddress((void**)&p_hres, g_hres);

    static cudaStream_t s1 = nullptr;
    static cudaEvent_t ev_fork = nullptr, ev_join = nullptr;
    if (s1 == nullptr) {
        cudaStreamCreateWithFlags(&s1, cudaStreamNonBlocking);
        cudaEventCreateWithFlags(&ev_fork, cudaEventDisableTiming);
        cudaEventCreateWithFlags(&ev_join, cudaEventDisableTiming);
    }

    cudaEventRecord(ev_fork, 0);
    cudaStreamWaitEvent(s1, ev_fork, 0);

    prep_kernel<<<(64 * 1024 + 8192 + 255) / 256, 256>>>(wfc, W1, W2);  // 1 (main)
    deg_kernel<<<(EE + 255) / 256, 256, 0, s1>>>(edst);                 // 2 (s1)
    scan1_kernel<<<NBLK_SCAN, 256, 0, s1>>>();                          // 3 (s1)

    // z = x @ WT  (A f32, C half row-major)   — launch 4 = profiled slot
    {
        dim3 grid(NTILES, 1);
        tgemm_kernel<0, 0, 1><<<grid, 256>>>(x, (const uint32_t*)p_wtp, p_zh,
                                             NN, DD, DD, nullptr, nullptr);
    }
    scan2_kernel<<<1, 256, 0, s1>>>();                                  // 5 (s1)
    eler_kernel<<<(NN * HH + 255) / 256, 256>>>(a_l, a_r);              // 6 (main)

    cudaEventRecord(ev_join, s1);
    cudaStreamWaitEvent(0, ev_join, 0);

    scatter_kernel<<<(EE + 255) / 256, 256>>>(esrc, edst);              // 7
    agg_ln_kernel<<<(NN + 7) / 8, 256>>>(x, gamma, beta);               // 8

    // inter = relu(ln @ W1 + b1)  (A frag, C frag for GEMM3)
    {
        dim3 grid(NTILES, DFF / 128);
        tgemm_kernel<1, 1, 2><<<grid, 256>>>(p_lnf, (const uint32_t*)p_w1p, p_intf,
                                             NN, DFF, DD, b1, nullptr);
    }
    // out = inter @ W2 + b2 + hres  (A frag, C f32 row-major)
    {
        dim3 grid(NTILES, 1);
        tgemm_kernel<2, 1, 0><<<grid, 256>>>(p_intf, (const uint32_t*)p_w2p, out,
                                             NN, DD, DFF, b2, p_hres);
    }
}

// round 15
// speedup vs baseline: 1.0623x; 1.0623x over previous
#include <cuda_runtime.h>
#include <cuda_fp16.h>
#include <math.h>
#include <stdint.h>

#define NN 50000
#define DD 128
#define HH 8
#define DHH 16
#define EE 800000
#define DFF 512
#define NBLK_SCAN 196   // ceil(50000/256)
#define NTILES 391      // ceil(50000/128)

// ---------------- scratch (static device globals; no allocation) ----------------
__device__ __half    g_zh[NN * DD];              // z, half, row-major
__device__ uint32_t  g_lnf[NTILES * 4 * 2048];   // LN out, A-fragment layout (K=128)
__device__ uint32_t  g_intf[NTILES * 16 * 2048]; // FFN inter, A-fragment layout (K=512)
__device__ uint32_t  g_wtp[4 * 2048];            // W_fc^T, B-fragment layout [c][2048]
__device__ uint32_t  g_w1p[4 * 4 * 2048];        // W1, B-fragment [c][nt][2048]
__device__ uint32_t  g_w2p[16 * 2048];           // W2, B-fragment [c][2048]
__device__ float g_el[NN * HH];
__device__ float g_er[NN * HH];
__device__ int   g_srcs[EE];
__device__ int   g_rank[EE];                     // edge rank within its dst segment
__device__ int   g_deg[NN];
__device__ int   g_base[NN];
__device__ int   g_bsum[256];
__device__ int   g_boff[256];
__device__ float g_hres[NN * DD];

__device__ __forceinline__ uint32_t f2h2(float lo, float hi) {
    __half2 h = __floats2half2_rn(lo, hi);
    return *(uint32_t*)&h;
}

// decode B-frag word index (within 2048-word block) -> (k0, n_local)
__device__ __forceinline__ void bfrag_decode(int rest, int& g, int& pl, int& nloc) {
    int blk = rest >> 6, off = rest & 63;
    g = blk >> 4;
    int u = blk & 15;
    int lw = off >> 1, iw = off & 1;
    pl = (lw & 3) + 4 * iw;
    nloc = u * 8 + (lw >> 2);
}

// ---------------- fused prep: zero counters + build fragment-layout weights ------
__global__ void prep_kernel(const float* __restrict__ wfc,
                            const float* __restrict__ W1,
                            const float* __restrict__ W2) {
    int i = blockIdx.x * blockDim.x + threadIdx.x;
    if (i < NN) g_deg[i] = 0;
    if (i < 4 * 2048) {
        int c = i >> 11, rest = i & 2047;
        int g, pl, n;
        bfrag_decode(rest, g, pl, n);
        int k0 = c * 32 + (g * 8 + pl) * 2;
        float v0 = wfc[(n >> 4) * 2048 + k0 * 16 + (n & 15)];
        float v1 = wfc[(n >> 4) * 2048 + (k0 + 1) * 16 + (n & 15)];
        g_wtp[i] = f2h2(v0, v1);
    }
    if (i < 4 * 4 * 2048) {
        int c = i >> 13, nt = (i >> 11) & 3, rest = i & 2047;
        int g, pl, nl;
        bfrag_decode(rest, g, pl, nl);
        int n = nt * 128 + nl;
        int k0 = c * 32 + (g * 8 + pl) * 2;
        g_w1p[i] = f2h2(W1[(size_t)k0 * DFF + n], W1[(size_t)(k0 + 1) * DFF + n]);
    }
    if (i < 16 * 2048) {
        int c = i >> 11, rest = i & 2047;
        int g, pl, n;
        bfrag_decode(rest, g, pl, n);
        int k0 = c * 32 + (g * 8 + pl) * 2;
        g_w2p[i] = f2h2(W2[(size_t)k0 * DD + n], W2[(size_t)(k0 + 1) * DD + n]);
    }
}

// ---------------- fp16 mma ----------------
__device__ __forceinline__ void mma_f16(float* c, const uint32_t* a, const uint32_t* b) {
    asm volatile(
        "mma.sync.aligned.m16n8k16.row.col.f32.f16.f16.f32 "
        "{%0,%1,%2,%3}, {%4,%5,%6,%7}, {%8,%9}, {%0,%1,%2,%3};"
        : "+f"(c[0]), "+f"(c[1]), "+f"(c[2]), "+f"(c[3])
        : "r"(a[0]), "r"(a[1]), "r"(a[2]), "r"(a[3]), "r"(b[0]), "r"(b[1]));
}

#define A_G_STRIDE 1028
#define B_U_STRIDE 68

// ---------------- fp16 tensor GEMM, 128x128 tile, 256 threads, smem dbuf ---------
template <int EPI, int AFRAG, int CMODE>
__global__ void __launch_bounds__(256, 2) tgemm_kernel(
    const void* __restrict__ Av, const uint32_t* __restrict__ Bp, void* __restrict__ Cv,
    int M, int Nn, int K, const float* __restrict__ bias, const float* __restrict__ res)
{
    __shared__ uint32_t Af[2][2 * A_G_STRIDE];
    __shared__ uint32_t Bf[2][2 * 16 * B_U_STRIDE];

    const float* A32 = (const float*)Av;
    const uint32_t* Afr = (const uint32_t*)Av;
    float* Cf = (float*)Cv;
    __half* Ch = (__half*)Cv;
    uint32_t* Cfr = (uint32_t*)Cv;

    const int tid = threadIdx.x;
    const int lane = tid & 31;
    const int wid = tid >> 5;
    const int wm = wid >> 2;
    const int wn = wid & 3;
    const int m0 = blockIdx.x * 128;
    const int n0 = blockIdx.y * 128;
    const int KC = K >> 5;
    const int NT = Nn >> 7;

    const int a_m = tid >> 3;
    const int a_kq = tid & 7;
    const int bblk = tid >> 4;
    const int boff = (4 * tid) & 63;

    uint32_t aw[8];
    uint4 av0, av1, bv0, bv1;

    auto ldg_chunk = [&](int c) {
        if constexpr (AFRAG) {
            const uint4* s = (const uint4*)(Afr + ((size_t)blockIdx.x * KC + c) * 2048);
            av0 = s[tid];
            av1 = s[tid + 256];
        } else {
            const int k0 = c * 32;
#pragma unroll
            for (int it = 0; it < 4; ++it) {
                int ml = a_m + it * 32;
                float4 v = make_float4(0.f, 0.f, 0.f, 0.f);
                if (m0 + ml < M) v = *(const float4*)&A32[(size_t)(m0 + ml) * K + k0 + a_kq * 4];
                aw[it * 2 + 0] = f2h2(v.x, v.y);
                aw[it * 2 + 1] = f2h2(v.z, v.w);
            }
        }
        const uint4* s = (const uint4*)(Bp + ((size_t)(c * NT + blockIdx.y)) * 2048);
        bv0 = s[tid];
        bv1 = s[tid + 256];
    };

    auto sts_chunk = [&](int buf) {
        if constexpr (AFRAG) {
            *(uint4*)&Af[buf][4 * tid] = av0;
            *(uint4*)&Af[buf][A_G_STRIDE + 4 * tid] = av1;
        } else {
#pragma unroll
            for (int it = 0; it < 4; ++it) {
                int ml = a_m + it * 32;
                int t4 = ml >> 4;
                int mr = ml & 15;
#pragma unroll
                for (int j = 0; j < 2; ++j) {
                    int p = 2 * a_kq + j;
                    int g = p >> 3, pl = p & 7;
                    int lw = (mr & 7) * 4 + (pl & 3);
                    int iw = (mr >> 3) + 2 * (pl >> 2);
                    Af[buf][g * A_G_STRIDE + t4 * 128 + lw * 4 + iw] = aw[it * 2 + j];
                }
            }
        }
        *(uint4*)&Bf[buf][bblk * B_U_STRIDE + boff] = bv0;
        *(uint4*)&Bf[buf][(16 + bblk) * B_U_STRIDE + boff] = bv1;
    };

    float acc[4][4][4];
#pragma unroll
    for (int i = 0; i < 4; ++i)
#pragma unroll
        for (int j = 0; j < 4; ++j)
#pragma unroll
            for (int r = 0; r < 4; ++r) acc[i][j][r] = 0.f;

    auto mma_chunk = [&](int buf) {
#pragma unroll
        for (int g = 0; g < 2; ++g) {
            uint32_t af[4][4], bf[4][2];
#pragma unroll
            for (int mt = 0; mt < 4; ++mt)
                *(uint4*)af[mt] = *(const uint4*)&Af[buf][g * A_G_STRIDE + (wm * 4 + mt) * 128 + lane * 4];
#pragma unroll
            for (int nt = 0; nt < 4; ++nt)
                *(uint2*)bf[nt] = *(const uint2*)&Bf[buf][(g * 16 + wn * 4 + nt) * B_U_STRIDE + lane * 2];
#pragma unroll
            for (int mt = 0; mt < 4; ++mt)
#pragma unroll
                for (int nt = 0; nt < 4; ++nt)
                    mma_f16(acc[mt][nt], af[mt], bf[nt]);
        }
    };

    ldg_chunk(0);
    sts_chunk(0);
    __syncthreads();
    for (int c = 1; c < KC; ++c) {
        ldg_chunk(c);
        mma_chunk((c - 1) & 1);
        sts_chunk(c & 1);
        __syncthreads();
    }
    mma_chunk((KC - 1) & 1);

    // epilogue
    const int lr = lane >> 2;
    const int lc = lane & 3;
#pragma unroll
    for (int mt = 0; mt < 4; ++mt) {
#pragma unroll
        for (int nt = 0; nt < 4; ++nt) {
            int row = m0 + wm * 64 + mt * 16 + lr;
            int col = n0 + wn * 32 + nt * 8 + 2 * lc;
            float c0 = acc[mt][nt][0], c1 = acc[mt][nt][1];
            float c2 = acc[mt][nt][2], c3 = acc[mt][nt][3];
            if (EPI == 1) {
                float b0 = bias[col], b1 = bias[col + 1];
                c0 = fmaxf(c0 + b0, 0.f); c1 = fmaxf(c1 + b1, 0.f);
                c2 = fmaxf(c2 + b0, 0.f); c3 = fmaxf(c3 + b1, 0.f);
            }
            if (EPI == 2) {
                float b0 = bias[col], b1 = bias[col + 1];
                if (row < M) {
                    c0 += b0 + res[(size_t)row * Nn + col];
                    c1 += b1 + res[(size_t)row * Nn + col + 1];
                }
                if (row + 8 < M) {
                    c2 += b0 + res[(size_t)(row + 8) * Nn + col];
                    c3 += b1 + res[(size_t)(row + 8) * Nn + col + 1];
                }
            }
            if (CMODE == 0) {
                if (row < M)     *(float2*)&Cf[(size_t)row * Nn + col]       = make_float2(c0, c1);
                if (row + 8 < M) *(float2*)&Cf[(size_t)(row + 8) * Nn + col] = make_float2(c2, c3);
            } else if (CMODE == 1) {
                if (row < M)     *(uint32_t*)&Ch[(size_t)row * Nn + col]       = f2h2(c0, c1);
                if (row + 8 < M) *(uint32_t*)&Ch[(size_t)(row + 8) * Nn + col] = f2h2(c2, c3);
            } else {
                int cc = col >> 5;
                int pw = (col >> 1) & 15;
                int gg = pw >> 3, pl = pw & 7;
                size_t base = ((size_t)blockIdx.x * (Nn >> 5) + cc) * 2048 + gg * 1024;
                int m = row & 127;
                int t4 = m >> 4, mr = m & 15;
                if (row < M)
                    Cfr[base + t4 * 128 + ((mr & 7) * 4 + (pl & 3)) * 4 + ((mr >> 3) + 2 * (pl >> 2))] = f2h2(c0, c1);
                int m2 = m + 8;
                int t42 = m2 >> 4, mr2 = m2 & 15;
                if (row + 8 < M)
                    Cfr[base + t42 * 128 + ((mr2 & 7) * 4 + (pl & 3)) * 4 + ((mr2 >> 3) + 2 * (pl >> 2))] = f2h2(c2, c3);
            }
        }
    }
}

// ---------------- el / er: one thread per (node, head), z half ----------------
__global__ void eler_kernel(const float* __restrict__ a_l, const float* __restrict__ a_r) {
    int idx = blockIdx.x * blockDim.x + threadIdx.x;
    if (idx >= NN * HH) return;
    int n = idx >> 3;
    int h = idx & 7;
    const uint32_t* zw = (const uint32_t*)&g_zh[n * DD + h * DHH];
    uint4 z0 = *(const uint4*)zw;
    uint4 z1 = *(const uint4*)(zw + 4);
    uint32_t w[8] = {z0.x, z0.y, z0.z, z0.w, z1.x, z1.y, z1.z, z1.w};
    const float* lp = &a_l[h * DHH];
    const float* rp = &a_r[h * DHH];
    float pl = 0.f, pr = 0.f;
#pragma unroll
    for (int q = 0; q < 8; ++q) {
        float2 f = __half22float2(*(__half2*)&w[q]);
        pl += f.x * lp[2 * q] + f.y * lp[2 * q + 1];
        pr += f.x * rp[2 * q] + f.y * rp[2 * q + 1];
    }
    g_el[idx] = pl;
    g_er[idx] = pr;
}

// ---------------- degree histogram + per-edge rank ----------------
__global__ void deg_kernel(const int* __restrict__ edst) {
    int e = blockIdx.x * blockDim.x + threadIdx.x;
    if (e >= EE) return;
    g_rank[e] = atomicAdd(&g_deg[edst[e]], 1);
}

// ---------------- scan (2 kernels; block-offset add folded into consumers) -------
__global__ void scan1_kernel() {
    __shared__ int sh[256];
    int t = threadIdx.x;
    int i = blockIdx.x * 256 + t;
    int v = (i < NN) ? g_deg[i] : 0;
    sh[t] = v;
    __syncthreads();
#pragma unroll
    for (int off = 1; off < 256; off <<= 1) {
        int x = (t >= off) ? sh[t - off] : 0;
        __syncthreads();
        sh[t] += x;
        __syncthreads();
    }
    if (i < NN) g_base[i] = sh[t] - v;
    if (t == 255) g_bsum[blockIdx.x] = sh[255];
}
__global__ void scan2_kernel() {
    __shared__ int sh[256];
    int t = threadIdx.x;
    int v = (t < NBLK_SCAN) ? g_bsum[t] : 0;
    sh[t] = v;
    __syncthreads();
#pragma unroll
    for (int off = 1; off < 256; off <<= 1) {
        int x = (t >= off) ? sh[t - off] : 0;
        __syncthreads();
        sh[t] += x;
        __syncthreads();
    }
    g_boff[t] = sh[t] - v;
}

// ---------------- slim scatter: index permute only ----------------
__global__ void scatter_kernel(const int* __restrict__ esrc, const int* __restrict__ edst) {
    int e = blockIdx.x * blockDim.x + threadIdx.x;
    if (e >= EE) return;
    int d = edst[e];
    g_srcs[g_base[d] + g_boff[d >> 8] + g_rank[e]] = esrc[e];
}

// ---------------- aggregation (on-the-fly weights) + elu + residual + LayerNorm --
__global__ void __launch_bounds__(256) agg_ln_kernel(
    const float* __restrict__ x,
    const float* __restrict__ gamma, const float* __restrict__ beta)
{
    __shared__ float sw[8 * 288];   // per warp: 32 edges x 9-stride (conflict-free)
    int warp = threadIdx.x >> 5;
    int lane = threadIdx.x & 31;
    int n = blockIdx.x * 8 + warp;
    if (n >= NN) return;
    float* swp = &sw[warp * 288];
    int start = g_base[n] + g_boff[n >> 8];
    int deg = g_deg[n];
    int h = lane >> 2;

    // er for this dst node (broadcast loads)
    float4 erv0 = *(const float4*)&g_er[n * HH];
    float4 erv1 = *(const float4*)&g_er[n * HH + 4];
    float er0 = erv0.x, er1 = erv0.y, er2 = erv0.z, er3 = erv0.w;
    float er4 = erv1.x, er5 = erv1.y, er6 = erv1.z, er7 = erv1.w;

    float4 acc = make_float4(0.f, 0.f, 0.f, 0.f);
    float s0 = 0.f, s1 = 0.f, s2 = 0.f, s3 = 0.f;
    float s4 = 0.f, s5 = 0.f, s6 = 0.f, s7 = 0.f;

    for (int b = 0; b < deg; b += 32) {
        int cnt = min(32, deg - b);
        int mysrc = 0;
        if (lane < cnt) {
            mysrc = g_srcs[start + b + lane];
            float4 elv0 = *(const float4*)&g_el[mysrc * HH];
            float4 elv1 = *(const float4*)&g_el[mysrc * HH + 4];
            float v, w;
            v = elv0.x + er0; v = (v > 0.f) ? v : 0.01f * v; w = __expf(v); s0 += w; swp[lane * 9 + 0] = w;
            v = elv0.y + er1; v = (v > 0.f) ? v : 0.01f * v; w = __expf(v); s1 += w; swp[lane * 9 + 1] = w;
            v = elv0.z + er2; v = (v > 0.f) ? v : 0.01f * v; w = __expf(v); s2 += w; swp[lane * 9 + 2] = w;
            v = elv0.w + er3; v = (v > 0.f) ? v : 0.01f * v; w = __expf(v); s3 += w; swp[lane * 9 + 3] = w;
            v = elv1.x + er4; v = (v > 0.f) ? v : 0.01f * v; w = __expf(v); s4 += w; swp[lane * 9 + 4] = w;
            v = elv1.y + er5; v = (v > 0.f) ? v : 0.01f * v; w = __expf(v); s5 += w; swp[lane * 9 + 5] = w;
            v = elv1.z + er6; v = (v > 0.f) ? v : 0.01f * v; w = __expf(v); s6 += w; swp[lane * 9 + 6] = w;
            v = elv1.w + er7; v = (v > 0.f) ? v : 0.01f * v; w = __expf(v); s7 += w; swp[lane * 9 + 7] = w;
        }
        __syncwarp();
#pragma unroll 4
        for (int j = 0; j < cnt; ++j) {
            int src = __shfl_sync(0xffffffffu, mysrc, j);
            float wv = swp[j * 9 + h];
            uint2 zv = *(const uint2*)&g_zh[(size_t)src * DD + lane * 4];
            float2 p0 = __half22float2(*(__half2*)&zv.x);
            float2 p1 = __half22float2(*(__half2*)&zv.y);
            acc.x = fmaf(wv, p0.x, acc.x);
            acc.y = fmaf(wv, p0.y, acc.y);
            acc.z = fmaf(wv, p1.x, acc.z);
            acc.w = fmaf(wv, p1.y, acc.w);
        }
        __syncwarp();
    }
    if (deg > 0) {
#pragma unroll
        for (int o = 16; o >= 1; o >>= 1) {
            s0 += __shfl_xor_sync(0xffffffffu, s0, o);
            s1 += __shfl_xor_sync(0xffffffffu, s1, o);
            s2 += __shfl_xor_sync(0xffffffffu, s2, o);
            s3 += __shfl_xor_sync(0xffffffffu, s3, o);
            s4 += __shfl_xor_sync(0xffffffffu, s4, o);
            s5 += __shfl_xor_sync(0xffffffffu, s5, o);
            s6 += __shfl_xor_sync(0xffffffffu, s6, o);
            s7 += __shfl_xor_sync(0xffffffffu, s7, o);
        }
        float sv;
        switch (h) {
            case 0: sv = s0; break;
            case 1: sv = s1; break;
            case 2: sv = s2; break;
            case 3: sv = s3; break;
            case 4: sv = s4; break;
            case 5: sv = s5; break;
            case 6: sv = s6; break;
            default: sv = s7; break;
        }
        float inv = 1.f / fmaxf(sv, 1e-9f);
        acc.x *= inv; acc.y *= inv; acc.z *= inv; acc.w *= inv;
    }
    // ---- fused elu + residual + LayerNorm, output in A-fragment layout ----
    float4 xv = ((const float4*)(x + (size_t)n * DD))[lane];
    float4 r;
    r.x = xv.x + (acc.x > 0.f ? acc.x : expm1f(acc.x));
    r.y = xv.y + (acc.y > 0.f ? acc.y : expm1f(acc.y));
    r.z = xv.z + (acc.z > 0.f ? acc.z : expm1f(acc.z));
    r.w = xv.w + (acc.w > 0.f ? acc.w : expm1f(acc.w));
    ((float4*)(g_hres + (size_t)n * DD))[lane] = r;
    float sum = r.x + r.y + r.z + r.w;
    float sq = r.x * r.x + r.y * r.y + r.z * r.z + r.w * r.w;
#pragma unroll
    for (int o = 16; o >= 1; o >>= 1) {
        sum += __shfl_xor_sync(0xffffffffu, sum, o);
        sq  += __shfl_xor_sync(0xffffffffu, sq, o);
    }
    float mu = sum * (1.f / 128.f);
    float var = sq * (1.f / 128.f) - mu * mu;
    float rstd = rsqrtf(var + 1e-5f);
    float4 gv = ((const float4*)gamma)[lane];
    float4 bv = ((const float4*)beta)[lane];
    float o0 = (r.x - mu) * rstd * gv.x + bv.x;
    float o1 = (r.y - mu) * rstd * gv.y + bv.y;
    float o2 = (r.z - mu) * rstd * gv.z + bv.z;
    float o3 = (r.w - mu) * rstd * gv.w + bv.w;
    int T = n >> 7, m = n & 127, t4 = m >> 4, mr = m & 15;
    uint32_t wA = f2h2(o0, o1), wB = f2h2(o2, o3);
    {
        int p = 2 * lane;
        int c = p >> 4, pw = p & 15, g = pw >> 3, pl = pw & 7;
        g_lnf[((size_t)T * 4 + c) * 2048 + g * 1024 + t4 * 128 +
              ((mr & 7) * 4 + (pl & 3)) * 4 + ((mr >> 3) + 2 * (pl >> 2))] = wA;
    }
    {
        int p = 2 * lane + 1;
        int c = p >> 4, pw = p & 15, g = pw >> 3, pl = pw & 7;
        g_lnf[((size_t)T * 4 + c) * 2048 + g * 1024 + t4 * 128 +
              ((mr & 7) * 4 + (pl & 3)) * 4 + ((mr >> 3) + 2 * (pl >> 2))] = wB;
    }
}

// ---------------- launch ----------------
extern "C" void kernel_launch(void* const* d_in, const int* in_sizes, int n_in,
                              void* d_out, int out_size) {
    const float* x      = (const float*)d_in[0];
    const float* wfc    = (const float*)d_in[1];
    const float* a_l    = (const float*)d_in[2];
    const float* a_r    = (const float*)d_in[3];
    const float* gamma  = (const float*)d_in[4];
    const float* beta   = (const float*)d_in[5];
    const float* W1     = (const float*)d_in[6];
    const float* b1     = (const float*)d_in[7];
    const float* W2     = (const float*)d_in[8];
    const float* b2     = (const float*)d_in[9];
    const int* esrc     = (const int*)d_in[10];
    const int* edst     = (const int*)d_in[11];
    float* out          = (float*)d_out;

    void *p_zh, *p_lnf, *p_intf, *p_wtp, *p_w1p, *p_w2p;
    float* p_hres;
    cudaGetSymbolAddress(&p_zh, g_zh);
    cudaGetSymbolAddress(&p_lnf, g_lnf);
    cudaGetSymbolAddress(&p_intf, g_intf);
    cudaGetSymbolAddress(&p_wtp, g_wtp);
    cudaGetSymbolAddress(&p_w1p, g_w1p);
    cudaGetSymbolAddress(&p_w2p, g_w2p);
    cudaGetSymbolAddress((void**)&p_hres, g_hres);

    static cudaStream_t s1 = nullptr;
    static cudaEvent_t ev_fork = nullptr, ev_join = nullptr;
    if (s1 == nullptr) {
        cudaStreamCreateWithFlags(&s1, cudaStreamNonBlocking);
        cudaEventCreateWithFlags(&ev_fork, cudaEventDisableTiming);
        cudaEventCreateWithFlags(&ev_join, cudaEventDisableTiming);
    }

    cudaEventRecord(ev_fork, 0);
    cudaStreamWaitEvent(s1, ev_fork, 0);

    prep_kernel<<<(64 * 1024 + 8192 + 255) / 256, 256>>>(wfc, W1, W2);  // 1 (main)
    deg_kernel<<<(EE + 255) / 256, 256, 0, s1>>>(edst);                 // 2 (s1)
    scan1_kernel<<<NBLK_SCAN, 256, 0, s1>>>();                          // 3 (s1)

    // z = x @ WT  (A f32, C half row-major)   — launch 4 = profiled slot
    {
        dim3 grid(NTILES, 1);
        tgemm_kernel<0, 0, 1><<<grid, 256>>>(x, (const uint32_t*)p_wtp, p_zh,
                                             NN, DD, DD, nullptr, nullptr);
    }
    scan2_kernel<<<1, 256, 0, s1>>>();                                  // 5 (s1)

    // slim scatter only needs edges + scan results -> run on s1 too
    scatter_kernel<<<(EE + 255) / 256, 256, 0, s1>>>(esrc, edst);       // 6 (s1)

    eler_kernel<<<(NN * HH + 255) / 256, 256>>>(a_l, a_r);              // 7 (main)

    cudaEventRecord(ev_join, s1);
    cudaStreamWaitEvent(0, ev_join, 0);

    agg_ln_kernel<<<(NN + 7) / 8, 256>>>(x, gamma, beta);               // 8

    // inter = relu(ln @ W1 + b1)  (A frag, C frag for GEMM3)
    {
        dim3 grid(NTILES, DFF / 128);
        tgemm_kernel<1, 1, 2><<<grid, 256>>>(p_lnf, (const uint32_t*)p_w1p, p_intf,
                                             NN, DFF, DD, b1, nullptr);
    }
    // out = inter @ W2 + b2 + hres  (A frag, C f32 row-major)
    {
        dim3 grid(NTILES, 1);
        tgemm_kernel<2, 1, 0><<<grid, 256>>>(p_intf, (const uint32_t*)p_w2p, out,
                                             NN, DD, DFF, b2, p_hres);
    }
}